// round 5
// baseline (speedup 1.0000x reference)
#include <cuda_runtime.h>
#include <cstdint>

#define BATCH  2
#define SEQ    2048
#define DMODEL 1024
#define NH     16
#define HD     64
#define MTOT   (BATCH*SEQ)     // 4096
#define LNEPS  1e-5f

// Scratch (allocation-free rule: __device__ globals)
__device__ float g_q[BATCH*NH*SEQ*HD];     // [BH][S][64]
__device__ float g_k[BATCH*NH*SEQ*HD];
__device__ float g_v[BATCH*NH*SEQ*HD];
__device__ float g_attn[(size_t)MTOT*DMODEL];

// ---------------------------------------------------------------------------
// Projection GEMM: C[m,n] = sum_k A[m,k] * W[n,k]   (A:[M,K] row, W:[N,K] row)
// MODE 0: out[((b*NH+h)*SEQ+s)*HD+e] = (C + bias[n]) * scale   (head scatter)
// MODE 1: out[m*D+n] = C + bias[n] + resid[m*D+n]
// BM=BN=128, BK=16, 256 threads, 8x8 per thread.
// ---------------------------------------------------------------------------
template<int MODE>
__global__ __launch_bounds__(256)
void proj_gemm(const float* __restrict__ A, const float* __restrict__ W,
               const float* __restrict__ bias, const float* __restrict__ resid,
               float* __restrict__ out, float scale)
{
    const int K = DMODEL;
    __shared__ float As[16][132];
    __shared__ float Bs[16][132];

    int tid = threadIdx.x;
    int m0 = blockIdx.y * 128;
    int n0 = blockIdx.x * 128;
    int tm = tid >> 4;          // 0..15
    int tn = tid & 15;          // 0..15

    float acc[8][8];
#pragma unroll
    for (int i = 0; i < 8; i++)
#pragma unroll
        for (int j = 0; j < 8; j++) acc[i][j] = 0.f;

    for (int k0 = 0; k0 < K; k0 += 16) {
#pragma unroll
        for (int it = 0; it < 2; it++) {
            int f   = tid + 256*it;       // 0..511
            int row = f >> 2;             // 0..127
            int cv  = (f & 3) * 4;        // 0,4,8,12
            float4 a = *(const float4*)&A[(size_t)(m0+row)*K + k0 + cv];
            As[cv+0][row]=a.x; As[cv+1][row]=a.y; As[cv+2][row]=a.z; As[cv+3][row]=a.w;
            float4 b = *(const float4*)&W[(size_t)(n0+row)*K + k0 + cv];
            Bs[cv+0][row]=b.x; Bs[cv+1][row]=b.y; Bs[cv+2][row]=b.z; Bs[cv+3][row]=b.w;
        }
        __syncthreads();
#pragma unroll
        for (int kk = 0; kk < 16; kk++) {
            float a[8], b[8];
            *(float4*)&a[0] = *(const float4*)&As[kk][tm*8];
            *(float4*)&a[4] = *(const float4*)&As[kk][tm*8+4];
            *(float4*)&b[0] = *(const float4*)&Bs[kk][tn*8];
            *(float4*)&b[4] = *(const float4*)&Bs[kk][tn*8+4];
#pragma unroll
            for (int i = 0; i < 8; i++)
#pragma unroll
                for (int j = 0; j < 8; j++) acc[i][j] += a[i]*b[j];
        }
        __syncthreads();
    }

    int n = n0 + tn*8;
    float4 bb0 = *(const float4*)&bias[n];
    float4 bb1 = *(const float4*)&bias[n+4];

#pragma unroll
    for (int i = 0; i < 8; i++) {
        int m = m0 + tm*8 + i;
        if (MODE == 0) {
            int b_ = m >> 11;            // m / SEQ
            int sr = m & (SEQ-1);
            int h  = n >> 6;
            int e  = n & 63;
            float* op = out + (((size_t)(b_*NH + h))*SEQ + sr)*HD + e;
            float4 r0, r1;
            r0.x=(acc[i][0]+bb0.x)*scale; r0.y=(acc[i][1]+bb0.y)*scale;
            r0.z=(acc[i][2]+bb0.z)*scale; r0.w=(acc[i][3]+bb0.w)*scale;
            r1.x=(acc[i][4]+bb1.x)*scale; r1.y=(acc[i][5]+bb1.y)*scale;
            r1.z=(acc[i][6]+bb1.z)*scale; r1.w=(acc[i][7]+bb1.w)*scale;
            *(float4*)op     = r0;
            *(float4*)(op+4) = r1;
        } else {
            size_t off = (size_t)m * DMODEL + n;
            float4 h0 = *(const float4*)&resid[off];
            float4 h1 = *(const float4*)&resid[off+4];
            float4 r0, r1;
            r0.x=acc[i][0]+bb0.x+h0.x; r0.y=acc[i][1]+bb0.y+h0.y;
            r0.z=acc[i][2]+bb0.z+h0.z; r0.w=acc[i][3]+bb0.w+h0.w;
            r1.x=acc[i][4]+bb1.x+h1.x; r1.y=acc[i][5]+bb1.y+h1.y;
            r1.z=acc[i][6]+bb1.z+h1.z; r1.w=acc[i][7]+bb1.w+h1.w;
            *(float4*)&out[off]   = r0;
            *(float4*)&out[off+4] = r1;
        }
    }
}

// ---------------------------------------------------------------------------
// Flash attention, fp32. One block per (q-tile of 64 rows, head) pair.
// 128 threads; thread owns 4 rows x 8 cols micro-tiles.
// scores = Q·K^T + extra_attn + mask  -> online softmax -> O += P·V
// Q already pre-scaled by hd^-0.5 in projection.
// ---------------------------------------------------------------------------
#define FA_SMEM ((3*64*64 + 64*65) * 4)

__global__ __launch_bounds__(128)
void flash_attn(const float* __restrict__ Q, const float* __restrict__ Kb,
                const float* __restrict__ Vb, const float* __restrict__ extra,
                const float* __restrict__ mask, float* __restrict__ out)
{
    extern __shared__ float sm[];
    float* QsT = sm;                 // [64 e][64 r]
    float* KsT = sm + 64*64;         // [64 e][64 c]
    float* Vs  = sm + 2*64*64;       // [64 c][64 d]
    float* PsT = sm + 3*64*64;       // [64 c][65 r] padded

    int tid = threadIdx.x;
    int rt  = tid >> 3;              // 0..15 -> rows rt*4..+3
    int ct  = tid & 7;               // 0..7  -> cols ct*8..+7
    int bh  = blockIdx.y;
    int b   = bh >> 4;
    int h   = bh & 15;
    int q0  = blockIdx.x * 64;

    const float* Qp = Q     + (size_t)bh * SEQ * HD;
    const float* Kp = Kb    + (size_t)bh * SEQ * HD;
    const float* Vp = Vb    + (size_t)bh * SEQ * HD;
    const float* Ep = extra + (size_t)bh * SEQ * SEQ;
    const float* Mp = mask  + (size_t)b  * SEQ * SEQ;

    // stage Q transposed: QsT[e][r] = Qp[q0+r][e]
#pragma unroll
    for (int i = 0; i < 8; i++) {
        int idx = tid*8 + i;
        int c   = idx >> 4;
        int ev  = (idx & 15) * 4;
        float4 v = *(const float4*)&Qp[(size_t)(q0 + c)*HD + ev];
        QsT[(ev+0)*64 + c] = v.x; QsT[(ev+1)*64 + c] = v.y;
        QsT[(ev+2)*64 + c] = v.z; QsT[(ev+3)*64 + c] = v.w;
    }

    float o[4][8];
    float mrow[4], lrow[4];
#pragma unroll
    for (int i = 0; i < 4; i++) {
        mrow[i] = -1e30f; lrow[i] = 0.f;
#pragma unroll
        for (int j = 0; j < 8; j++) o[i][j] = 0.f;
    }

    for (int k0 = 0; k0 < SEQ; k0 += 64) {
        __syncthreads();   // previous PV gemm done (and Q staging on iter 0)
#pragma unroll
        for (int i = 0; i < 8; i++) {
            int idx = tid*8 + i;
            int c   = idx >> 4;
            int ev  = (idx & 15) * 4;
            float4 kv = *(const float4*)&Kp[(size_t)(k0 + c)*HD + ev];
            KsT[(ev+0)*64 + c] = kv.x; KsT[(ev+1)*64 + c] = kv.y;
            KsT[(ev+2)*64 + c] = kv.z; KsT[(ev+3)*64 + c] = kv.w;
            float4 vv = *(const float4*)&Vp[(size_t)(k0 + c)*HD + ev];
            *(float4*)&Vs[c*64 + ev] = vv;
        }
        __syncthreads();

        // S = Q K^T  (4x8 per thread)
        float s[4][8];
#pragma unroll
        for (int i = 0; i < 4; i++)
#pragma unroll
            for (int j = 0; j < 8; j++) s[i][j] = 0.f;

#pragma unroll 8
        for (int e = 0; e < 64; e++) {
            float4 qa = *(const float4*)&QsT[e*64 + rt*4];
            float4 b0 = *(const float4*)&KsT[e*64 + ct*8];
            float4 b1 = *(const float4*)&KsT[e*64 + ct*8 + 4];
            float aa[4] = {qa.x, qa.y, qa.z, qa.w};
            float bb[8] = {b0.x,b0.y,b0.z,b0.w,b1.x,b1.y,b1.z,b1.w};
#pragma unroll
            for (int i = 0; i < 4; i++)
#pragma unroll
                for (int j = 0; j < 8; j++) s[i][j] += aa[i]*bb[j];
        }

        // + extra_attn + attention_mask
#pragma unroll
        for (int i = 0; i < 4; i++) {
            int row = q0 + rt*4 + i;
            const float* ep = Ep + (size_t)row*SEQ + k0 + ct*8;
            const float* mp = Mp + (size_t)row*SEQ + k0 + ct*8;
            float4 e0 = *(const float4*)ep;
            float4 e1 = *(const float4*)(ep+4);
            float4 m0 = *(const float4*)mp;
            float4 m1 = *(const float4*)(mp+4);
            s[i][0]+=e0.x+m0.x; s[i][1]+=e0.y+m0.y; s[i][2]+=e0.z+m0.z; s[i][3]+=e0.w+m0.w;
            s[i][4]+=e1.x+m1.x; s[i][5]+=e1.y+m1.y; s[i][6]+=e1.z+m1.z; s[i][7]+=e1.w+m1.w;
        }

        // online softmax (row stats reduced over the 8-lane col group)
#pragma unroll
        for (int i = 0; i < 4; i++) {
            float tmx = s[i][0];
#pragma unroll
            for (int j = 1; j < 8; j++) tmx = fmaxf(tmx, s[i][j]);
            tmx = fmaxf(tmx, __shfl_xor_sync(0xffffffffu, tmx, 1));
            tmx = fmaxf(tmx, __shfl_xor_sync(0xffffffffu, tmx, 2));
            tmx = fmaxf(tmx, __shfl_xor_sync(0xffffffffu, tmx, 4));
            float mn    = fmaxf(mrow[i], tmx);
            float alpha = __expf(mrow[i] - mn);
            mrow[i] = mn;
            float sum = 0.f;
#pragma unroll
            for (int j = 0; j < 8; j++) {
                float p = __expf(s[i][j] - mn);
                s[i][j] = p;
                sum += p;
            }
            sum += __shfl_xor_sync(0xffffffffu, sum, 1);
            sum += __shfl_xor_sync(0xffffffffu, sum, 2);
            sum += __shfl_xor_sync(0xffffffffu, sum, 4);
            lrow[i] = lrow[i]*alpha + sum;
#pragma unroll
            for (int j = 0; j < 8; j++) o[i][j] *= alpha;
#pragma unroll
            for (int j = 0; j < 8; j++)
                PsT[(ct*8 + j)*65 + rt*4 + i] = s[i][j];
        }
        __syncthreads();

        // O += P V
#pragma unroll 4
        for (int c = 0; c < 64; c++) {
            float pa[4];
#pragma unroll
            for (int i = 0; i < 4; i++) pa[i] = PsT[c*65 + rt*4 + i];
            float4 v0 = *(const float4*)&Vs[c*64 + ct*8];
            float4 v1 = *(const float4*)&Vs[c*64 + ct*8 + 4];
            float vb[8] = {v0.x,v0.y,v0.z,v0.w,v1.x,v1.y,v1.z,v1.w};
#pragma unroll
            for (int i = 0; i < 4; i++)
#pragma unroll
                for (int j = 0; j < 8; j++) o[i][j] += pa[i]*vb[j];
        }
    }

    // epilogue: normalize and scatter to [B,S,D] (D index = h*64 + e)
#pragma unroll
    for (int i = 0; i < 4; i++) {
        int sr = q0 + rt*4 + i;
        float inv = 1.0f / lrow[i];
        float4 r0, r1;
        r0.x=o[i][0]*inv; r0.y=o[i][1]*inv; r0.z=o[i][2]*inv; r0.w=o[i][3]*inv;
        r1.x=o[i][4]*inv; r1.y=o[i][5]*inv; r1.z=o[i][6]*inv; r1.w=o[i][7]*inv;
        float* op = out + ((size_t)(b*SEQ + sr))*DMODEL + h*HD + ct*8;
        *(float4*)op     = r0;
        *(float4*)(op+4) = r1;
    }
}

// ---------------------------------------------------------------------------
// In-place LayerNorm over rows of x (written by proj_gemm<1> into d_out)
// ---------------------------------------------------------------------------
__global__ __launch_bounds__(256)
void ln_kernel(float* __restrict__ x, const float* __restrict__ gamma,
               const float* __restrict__ beta)
{
    __shared__ float red[8];
    int row = blockIdx.x, tid = threadIdx.x;
    float4* xr = (float4*)(x + (size_t)row * DMODEL);
    float4 v = xr[tid];

    float s = v.x + v.y + v.z + v.w;
#pragma unroll
    for (int off = 16; off; off >>= 1) s += __shfl_xor_sync(0xffffffffu, s, off);
    if ((tid & 31) == 0) red[tid >> 5] = s;
    __syncthreads();
    float tot = 0.f;
#pragma unroll
    for (int w = 0; w < 8; w++) tot += red[w];
    float mu = tot * (1.0f / DMODEL);

    float dx=v.x-mu, dy=v.y-mu, dz=v.z-mu, dw=v.w-mu;
    float s2 = dx*dx + dy*dy + dz*dz + dw*dw;
#pragma unroll
    for (int off = 16; off; off >>= 1) s2 += __shfl_xor_sync(0xffffffffu, s2, off);
    __syncthreads();
    if ((tid & 31) == 0) red[tid >> 5] = s2;
    __syncthreads();
    float tot2 = 0.f;
#pragma unroll
    for (int w = 0; w < 8; w++) tot2 += red[w];
    float rs = rsqrtf(tot2 * (1.0f / DMODEL) + LNEPS);

    float4 g = ((const float4*)gamma)[tid];
    float4 bb = ((const float4*)beta)[tid];
    float4 r;
    r.x = dx*rs*g.x + bb.x;
    r.y = dy*rs*g.y + bb.y;
    r.z = dz*rs*g.z + bb.z;
    r.w = dw*rs*g.w + bb.w;
    xr[tid] = r;
}

// ---------------------------------------------------------------------------
extern "C" void kernel_launch(void* const* d_in, const int* in_sizes, int n_in,
                              void* d_out, int out_size)
{
    const float* hidden = (const float*)d_in[0];
    const float* mask   = (const float*)d_in[1];
    const float* extra  = (const float*)d_in[2];
    const float* Wq     = (const float*)d_in[3];
    const float* bq     = (const float*)d_in[4];
    const float* Wk     = (const float*)d_in[5];
    const float* bk     = (const float*)d_in[6];
    const float* Wv     = (const float*)d_in[7];
    const float* bv     = (const float*)d_in[8];
    const float* Wo     = (const float*)d_in[9];
    const float* bo     = (const float*)d_in[10];
    const float* gamma  = (const float*)d_in[11];
    const float* beta   = (const float*)d_in[12];
    float* out = (float*)d_out;

    float *q, *k, *v, *attn;
    cudaGetSymbolAddress((void**)&q,    g_q);
    cudaGetSymbolAddress((void**)&k,    g_k);
    cudaGetSymbolAddress((void**)&v,    g_v);
    cudaGetSymbolAddress((void**)&attn, g_attn);

    const float scaling = 0.125f;   // hd^-0.5, hd=64

    dim3 pg(DMODEL/128, MTOT/128);  // (8, 32)
    proj_gemm<0><<<pg, 256>>>(hidden, Wq, bq, nullptr, q, scaling);
    proj_gemm<0><<<pg, 256>>>(hidden, Wk, bk, nullptr, k, 1.0f);
    proj_gemm<0><<<pg, 256>>>(hidden, Wv, bv, nullptr, v, 1.0f);

    cudaFuncSetAttribute(flash_attn, cudaFuncAttributeMaxDynamicSharedMemorySize, FA_SMEM);
    flash_attn<<<dim3(SEQ/64, BATCH*NH), 128, FA_SMEM>>>(q, k, v, extra, mask, attn);

    proj_gemm<1><<<pg, 256>>>(attn, Wo, bo, hidden, out, 1.0f);
    ln_kernel<<<MTOT, 256>>>(out, gamma, beta);
}

// round 8
// speedup vs baseline: 5.8062x; 5.8062x over previous
#include <cuda_runtime.h>
#include <cuda_bf16.h>
#include <cstdint>

#define BATCH  2
#define SEQ    2048
#define DMODEL 1024
#define NH     16
#define HD     64
#define MTOT   (BATCH*SEQ)     // 4096
#define LNEPS  1e-5f

typedef __nv_bfloat16  bf16;
typedef __nv_bfloat162 bf162;

// ---------------- scratch (__device__ globals; no allocs allowed) -----------
__device__ bf16 g_hb[(size_t)MTOT*DMODEL];   // hidden in bf16
__device__ bf16 g_wq[DMODEL*DMODEL];
__device__ bf16 g_wk[DMODEL*DMODEL];
__device__ bf16 g_wv[DMODEL*DMODEL];
__device__ bf16 g_wo[DMODEL*DMODEL];
__device__ bf16 g_q[(size_t)BATCH*NH*SEQ*HD];   // [BH][S][64]
__device__ bf16 g_k[(size_t)BATCH*NH*SEQ*HD];
__device__ bf16 g_v[(size_t)BATCH*NH*SEQ*HD];
__device__ bf16 g_attn[(size_t)MTOT*DMODEL];    // flash output, row-major

// ---------------- small helpers --------------------------------------------
__device__ __forceinline__ uint32_t s2u(const void* p) {
    return (uint32_t)__cvta_generic_to_shared(p);
}
__device__ __forceinline__ void ldsm4(uint32_t& r0, uint32_t& r1,
                                      uint32_t& r2, uint32_t& r3, uint32_t a) {
    asm volatile("ldmatrix.sync.aligned.m8n8.x4.shared.b16 {%0,%1,%2,%3},[%4];"
                 : "=r"(r0), "=r"(r1), "=r"(r2), "=r"(r3) : "r"(a));
}
__device__ __forceinline__ void ldsm4t(uint32_t& r0, uint32_t& r1,
                                       uint32_t& r2, uint32_t& r3, uint32_t a) {
    asm volatile("ldmatrix.sync.aligned.m8n8.x4.trans.shared.b16 {%0,%1,%2,%3},[%4];"
                 : "=r"(r0), "=r"(r1), "=r"(r2), "=r"(r3) : "r"(a));
}
__device__ __forceinline__ void mma16816(float* c, const uint32_t* a, const uint32_t* b) {
    asm volatile(
        "mma.sync.aligned.m16n8k16.row.col.f32.bf16.bf16.f32 "
        "{%0,%1,%2,%3},{%4,%5,%6,%7},{%8,%9},{%0,%1,%2,%3};"
        : "+f"(c[0]), "+f"(c[1]), "+f"(c[2]), "+f"(c[3])
        : "r"(a[0]), "r"(a[1]), "r"(a[2]), "r"(a[3]), "r"(b[0]), "r"(b[1]));
}
__device__ __forceinline__ void cp16(uint32_t s, const void* g) {
    asm volatile("cp.async.cg.shared.global [%0],[%1],16;" :: "r"(s), "l"(g));
}
__device__ __forceinline__ uint32_t packbf(float a, float b) {
    bf162 t = __floats2bfloat162_rn(a, b);   // .x = a (low half = first k)
    return *(uint32_t*)&t;
}

// ---------------- fp32 -> bf16 convert --------------------------------------
__global__ void f2bf_kernel(const float4* __restrict__ x, bf162* __restrict__ y, int n4) {
    int i = blockIdx.x * blockDim.x + threadIdx.x;
    if (i < n4) {
        float4 v = x[i];
        y[2*i]   = __floats2bfloat162_rn(v.x, v.y);
        y[2*i+1] = __floats2bfloat162_rn(v.z, v.w);
    }
}

// ---------------------------------------------------------------------------
// bf16 GEMM: C[m,n] = sum_k A[m,k]*W[n,k], fp32 accum.
// BM=BN=128, BK=64, 256 threads (warp grid 4m x 2n, warp tile 32x64).
// MODE 0: out bf16 head-scatter, (acc+bias)*scale
// MODE 1: out fp32 [M][D], acc+bias+resid
// Dynamic smem: 2 stages x (A 16KB + B 16KB) = 64KB
// ---------------------------------------------------------------------------
template<int MODE>
__global__ __launch_bounds__(256, 2)
void gemm_bf16(const bf16* __restrict__ A, const bf16* __restrict__ W,
               const float* __restrict__ bias, const float* __restrict__ resid,
               void* __restrict__ outv, float scale)
{
    extern __shared__ char sm[];
    const uint32_t sbase = s2u(sm);
    const int tid = threadIdx.x;
    const int wid = tid >> 5, lane = tid & 31;
    const int wm = wid >> 1, wn = wid & 1;
    const int m0 = blockIdx.y * 128, n0 = blockIdx.x * 128;

    float c[2][8][4];
#pragma unroll
    for (int mf = 0; mf < 2; mf++)
#pragma unroll
        for (int j = 0; j < 8; j++)
#pragma unroll
            for (int t = 0; t < 4; t++) c[mf][j][t] = 0.f;

    auto load_stage = [&](int s, int k0) {
        uint32_t ba = sbase + s * 32768;
        uint32_t bb = ba + 16384;
#pragma unroll
        for (int i = 0; i < 4; i++) {
            int idx = tid + 256 * i;           // 0..1023
            int row = idx >> 3, ch = idx & 7;
            uint32_t off = row * 128 + ((ch ^ (row & 7)) << 4);
            cp16(ba + off, A + (size_t)(m0 + row) * DMODEL + k0 + ch * 8);
            cp16(bb + off, W + (size_t)(n0 + row) * DMODEL + k0 + ch * 8);
        }
        asm volatile("cp.async.commit_group;");
    };

    load_stage(0, 0);

    for (int kt = 0; kt < 16; kt++) {
        if (kt < 15) {
            load_stage((kt + 1) & 1, (kt + 1) * 64);
            asm volatile("cp.async.wait_group 1;");
        } else {
            asm volatile("cp.async.wait_group 0;");
        }
        __syncthreads();
        uint32_t ba = sbase + (kt & 1) * 32768;
        uint32_t bb = ba + 16384;
#pragma unroll
        for (int kk = 0; kk < 4; kk++) {
            uint32_t a[2][4], b[8][2];
            int g = lane >> 3;
#pragma unroll
            for (int mf = 0; mf < 2; mf++) {
                int row = wm * 32 + mf * 16 + ((g & 1) << 3) + (lane & 7);
                int ch  = 2 * kk + (g >> 1);
                ldsm4(a[mf][0], a[mf][1], a[mf][2], a[mf][3],
                      ba + row * 128 + ((ch ^ (row & 7)) << 4));
            }
#pragma unroll
            for (int jp = 0; jp < 4; jp++) {
                int row = wn * 64 + jp * 16 + ((g >> 1) << 3) + (lane & 7);
                int ch  = 2 * kk + (g & 1);
                ldsm4(b[2*jp][0], b[2*jp][1], b[2*jp+1][0], b[2*jp+1][1],
                      bb + row * 128 + ((ch ^ (row & 7)) << 4));
            }
#pragma unroll
            for (int mf = 0; mf < 2; mf++)
#pragma unroll
                for (int j = 0; j < 8; j++)
                    mma16816(c[mf][j], a[mf], b[j]);
        }
        __syncthreads();
    }

    // epilogue
    const int r = lane >> 2, cq = lane & 3;
#pragma unroll
    for (int mf = 0; mf < 2; mf++) {
#pragma unroll
        for (int j = 0; j < 8; j++) {
            int ng = n0 + wn * 64 + j * 8 + 2 * cq;
            float b0 = bias[ng], b1 = bias[ng + 1];
#pragma unroll
            for (int half = 0; half < 2; half++) {
                int mg = m0 + wm * 32 + mf * 16 + r + half * 8;
                float v0 = c[mf][j][half*2+0] + b0;
                float v1 = c[mf][j][half*2+1] + b1;
                if (MODE == 0) {
                    v0 *= scale; v1 *= scale;
                    int b_ = mg >> 11, sr = mg & (SEQ - 1);
                    int h  = ng >> 6,  e  = ng & 63;
                    bf162* op = (bf162*)((bf16*)outv +
                        (((size_t)(b_ * NH + h)) * SEQ + sr) * HD + e);
                    *op = __floats2bfloat162_rn(v0, v1);
                } else {
                    size_t off = (size_t)mg * DMODEL + ng;
                    float2 hres = *(const float2*)&resid[off];
                    float2 o; o.x = v0 + hres.x; o.y = v1 + hres.y;
                    *(float2*)((float*)outv + off) = o;
                }
            }
        }
    }
}

// ---------------------------------------------------------------------------
// Flash attention with HMMA. 64 q-rows per block, 4 warps (warp = 16 rows).
// Dynamic smem: Q(8KB) + 2 stages x (K 8KB + V 8KB + E 64x68 fp32 17KB)
// ---------------------------------------------------------------------------
#define FLASH_SMEM (8192 + 2*(8192 + 8192 + 17408))

__global__ __launch_bounds__(128)
void flash_mma(const bf16* __restrict__ Q, const bf16* __restrict__ K,
               const bf16* __restrict__ V, const float* __restrict__ extra,
               const float* __restrict__ mask, bf16* __restrict__ out)
{
    extern __shared__ char sm[];
    const uint32_t sbase = s2u(sm);
    const int tid = threadIdx.x, wid = tid >> 5, lane = tid & 31;
    const int bh = blockIdx.y, b = bh >> 4, h = bh & 15;
    const int q0 = blockIdx.x * 64;

    const bf16* Qp = Q + (size_t)bh * SEQ * HD;
    const bf16* Kp = K + (size_t)bh * SEQ * HD;
    const bf16* Vp = V + (size_t)bh * SEQ * HD;
    const float* Ep = extra + (size_t)bh * SEQ * SEQ;
    const float* Mp = mask  + (size_t)b  * SEQ * SEQ;

    // stage byte bases
    auto stK = [&](int s) { return sbase + 8192 + s * 33792; };
    auto stV = [&](int s) { return sbase + 8192 + s * 33792 + 8192; };
    auto stE = [&](int s) { return sbase + 8192 + s * 33792 + 16384; };

    // Q tile -> smem (swizzled), direct loads
#pragma unroll
    for (int i = 0; i < 4; i++) {
        int idx = tid + 128 * i;
        int row = idx >> 3, ch = idx & 7;
        uint32_t off = row * 128 + ((ch ^ (row & 7)) << 4);
        *(int4*)(sm + off) = *(const int4*)(Qp + (size_t)(q0 + row) * HD + ch * 8);
    }

    auto load_stage = [&](int s, int k0) {
        uint32_t bk = stK(s), bv = stV(s), be = stE(s);
#pragma unroll
        for (int i = 0; i < 4; i++) {
            int idx = tid + 128 * i;
            int row = idx >> 3, ch = idx & 7;
            uint32_t off = row * 128 + ((ch ^ (row & 7)) << 4);
            cp16(bk + off, Kp + (size_t)(k0 + row) * HD + ch * 8);
            cp16(bv + off, Vp + (size_t)(k0 + row) * HD + ch * 8);
        }
#pragma unroll
        for (int i = 0; i < 8; i++) {
            int idx = tid + 128 * i;           // 1024 chunks of E
            int row = idx >> 4, ch = idx & 15;
            cp16(be + row * 272 + ch * 16,
                 Ep + (size_t)(q0 + row) * SEQ + k0 + ch * 4);
        }
        asm volatile("cp.async.commit_group;");
    };

    load_stage(0, 0);
    __syncthreads();   // Q stores visible

    // hoist Q fragments
    uint32_t qf[4][4];
    {
        int g = lane >> 3;
#pragma unroll
        for (int kk = 0; kk < 4; kk++) {
            int row = wid * 16 + ((g & 1) << 3) + (lane & 7);
            int ch  = 2 * kk + (g >> 1);
            ldsm4(qf[kk][0], qf[kk][1], qf[kk][2], qf[kk][3],
                  sbase + row * 128 + ((ch ^ (row & 7)) << 4));
        }
    }

    float o[8][4];
#pragma unroll
    for (int j = 0; j < 8; j++)
#pragma unroll
        for (int t = 0; t < 4; t++) o[j][t] = 0.f;
    float mrow0 = -1e30f, mrow1 = -1e30f, lrow0 = 0.f, lrow1 = 0.f;
    const int r = lane >> 2, cq = lane & 3;

    for (int kt = 0; kt < 32; kt++) {
        if (kt < 31) {
            load_stage((kt + 1) & 1, (kt + 1) * 64);
            asm volatile("cp.async.wait_group 1;");
        } else {
            asm volatile("cp.async.wait_group 0;");
        }
        __syncthreads();
        const int st = kt & 1;
        uint32_t bk = stK(st), bv = stV(st);
        char* be = sm + 8192 + st * 33792 + 16384;

        // ---- S = Q K^T ----
        float s[8][4];
#pragma unroll
        for (int j = 0; j < 8; j++)
#pragma unroll
            for (int t = 0; t < 4; t++) s[j][t] = 0.f;

        int g = lane >> 3;
#pragma unroll
        for (int kk = 0; kk < 4; kk++) {
            uint32_t kb[8][2];
#pragma unroll
            for (int jp = 0; jp < 4; jp++) {
                int row = jp * 16 + ((g >> 1) << 3) + (lane & 7);
                int ch  = 2 * kk + (g & 1);
                ldsm4(kb[2*jp][0], kb[2*jp][1], kb[2*jp+1][0], kb[2*jp+1][1],
                      bk + row * 128 + ((ch ^ (row & 7)) << 4));
            }
#pragma unroll
            for (int j = 0; j < 8; j++) mma16816(s[j], qf[kk], kb[j]);
        }

        // ---- add extra (smem, fp32) + mask (gmem, L2-hot) ----
#pragma unroll
        for (int j = 0; j < 8; j++) {
            int col = j * 8 + 2 * cq;
            int wr  = wid * 16 + r;
            float2 e0 = *(float2*)(be + wr * 272 + col * 4);
            float2 e1 = *(float2*)(be + (wr + 8) * 272 + col * 4);
            const float* mp0 = Mp + (size_t)(q0 + wr) * SEQ + kt * 64 + col;
            float2 m0 = *(const float2*)mp0;
            float2 m1 = *(const float2*)(mp0 + 8 * SEQ);
            s[j][0] += e0.x + m0.x;  s[j][1] += e0.y + m0.y;
            s[j][2] += e1.x + m1.x;  s[j][3] += e1.y + m1.y;
        }

        // ---- online softmax (rows r, r+8; quad lanes share a row) ----
        float mx0 = s[0][0], mx1 = s[0][2];
#pragma unroll
        for (int j = 0; j < 8; j++) {
            mx0 = fmaxf(mx0, fmaxf(s[j][0], s[j][1]));
            mx1 = fmaxf(mx1, fmaxf(s[j][2], s[j][3]));
        }
        mx0 = fmaxf(mx0, __shfl_xor_sync(0xffffffffu, mx0, 1));
        mx0 = fmaxf(mx0, __shfl_xor_sync(0xffffffffu, mx0, 2));
        mx1 = fmaxf(mx1, __shfl_xor_sync(0xffffffffu, mx1, 1));
        mx1 = fmaxf(mx1, __shfl_xor_sync(0xffffffffu, mx1, 2));
        float mn0 = fmaxf(mrow0, mx0), mn1 = fmaxf(mrow1, mx1);
        float al0 = __expf(mrow0 - mn0), al1 = __expf(mrow1 - mn1);
        mrow0 = mn0; mrow1 = mn1;
        float sum0 = 0.f, sum1 = 0.f;
#pragma unroll
        for (int j = 0; j < 8; j++) {
            s[j][0] = __expf(s[j][0] - mn0); sum0 += s[j][0];
            s[j][1] = __expf(s[j][1] - mn0); sum0 += s[j][1];
            s[j][2] = __expf(s[j][2] - mn1); sum1 += s[j][2];
            s[j][3] = __expf(s[j][3] - mn1); sum1 += s[j][3];
        }
        sum0 += __shfl_xor_sync(0xffffffffu, sum0, 1);
        sum0 += __shfl_xor_sync(0xffffffffu, sum0, 2);
        sum1 += __shfl_xor_sync(0xffffffffu, sum1, 1);
        sum1 += __shfl_xor_sync(0xffffffffu, sum1, 2);
        lrow0 = lrow0 * al0 + sum0;
        lrow1 = lrow1 * al1 + sum1;
#pragma unroll
        for (int j = 0; j < 8; j++) {
            o[j][0] *= al0; o[j][1] *= al0;
            o[j][2] *= al1; o[j][3] *= al1;
        }

        // ---- repack P -> bf16 A-fragments ----
        uint32_t p[4][4];
#pragma unroll
        for (int t = 0; t < 4; t++) {
            p[t][0] = packbf(s[2*t][0],   s[2*t][1]);
            p[t][1] = packbf(s[2*t][2],   s[2*t][3]);
            p[t][2] = packbf(s[2*t+1][0], s[2*t+1][1]);
            p[t][3] = packbf(s[2*t+1][2], s[2*t+1][3]);
        }

        // ---- O += P V ----
#pragma unroll
        for (int t = 0; t < 4; t++) {
            uint32_t vb[8][2];
#pragma unroll
            for (int jp = 0; jp < 4; jp++) {
                int row = t * 16 + ((g & 1) << 3) + (lane & 7);
                int ch  = 2 * jp + (g >> 1);
                ldsm4t(vb[2*jp][0], vb[2*jp][1], vb[2*jp+1][0], vb[2*jp+1][1],
                       bv + row * 128 + ((ch ^ (row & 7)) << 4));
            }
#pragma unroll
            for (int j = 0; j < 8; j++) mma16816(o[j], p[t], vb[j]);
        }
        __syncthreads();
    }

    // ---- epilogue: normalize, write bf16 to [B,S,D] ----
    float inv0 = 1.0f / lrow0, inv1 = 1.0f / lrow1;
#pragma unroll
    for (int j = 0; j < 8; j++) {
        int d = h * 64 + j * 8 + 2 * cq;
        int row0 = q0 + wid * 16 + r;
        bf162* p0 = (bf162*)(out + (size_t)(b * SEQ + row0) * DMODEL + d);
        bf162* p1 = (bf162*)(out + (size_t)(b * SEQ + row0 + 8) * DMODEL + d);
        *p0 = __floats2bfloat162_rn(o[j][0] * inv0, o[j][1] * inv0);
        *p1 = __floats2bfloat162_rn(o[j][2] * inv1, o[j][3] * inv1);
    }
}

// ---------------------------------------------------------------------------
// In-place LayerNorm
// ---------------------------------------------------------------------------
__global__ __launch_bounds__(256)
void ln_kernel(float* __restrict__ x, const float* __restrict__ gamma,
               const float* __restrict__ beta)
{
    __shared__ float red[8];
    int row = blockIdx.x, tid = threadIdx.x;
    float4* xr = (float4*)(x + (size_t)row * DMODEL);
    float4 v = xr[tid];

    float s = v.x + v.y + v.z + v.w;
#pragma unroll
    for (int off = 16; off; off >>= 1) s += __shfl_xor_sync(0xffffffffu, s, off);
    if ((tid & 31) == 0) red[tid >> 5] = s;
    __syncthreads();
    float tot = 0.f;
#pragma unroll
    for (int w = 0; w < 8; w++) tot += red[w];
    float mu = tot * (1.0f / DMODEL);

    float dx = v.x - mu, dy = v.y - mu, dz = v.z - mu, dw = v.w - mu;
    float s2 = dx*dx + dy*dy + dz*dz + dw*dw;
#pragma unroll
    for (int off = 16; off; off >>= 1) s2 += __shfl_xor_sync(0xffffffffu, s2, off);
    __syncthreads();
    if ((tid & 31) == 0) red[tid >> 5] = s2;
    __syncthreads();
    float tot2 = 0.f;
#pragma unroll
    for (int w = 0; w < 8; w++) tot2 += red[w];
    float rs = rsqrtf(tot2 * (1.0f / DMODEL) + LNEPS);

    float4 gmm = ((const float4*)gamma)[tid];
    float4 bb  = ((const float4*)beta)[tid];
    float4 rr;
    rr.x = dx * rs * gmm.x + bb.x;
    rr.y = dy * rs * gmm.y + bb.y;
    rr.z = dz * rs * gmm.z + bb.z;
    rr.w = dw * rs * gmm.w + bb.w;
    xr[tid] = rr;
}

// ---------------------------------------------------------------------------
extern "C" void kernel_launch(void* const* d_in, const int* in_sizes, int n_in,
                              void* d_out, int out_size)
{
    const float* hidden = (const float*)d_in[0];
    const float* mask   = (const float*)d_in[1];
    const float* extra  = (const float*)d_in[2];
    const float* Wq     = (const float*)d_in[3];
    const float* bq     = (const float*)d_in[4];
    const float* Wk     = (const float*)d_in[5];
    const float* bk     = (const float*)d_in[6];
    const float* Wv     = (const float*)d_in[7];
    const float* bv     = (const float*)d_in[8];
    const float* Wo     = (const float*)d_in[9];
    const float* bo     = (const float*)d_in[10];
    const float* gamma  = (const float*)d_in[11];
    const float* beta   = (const float*)d_in[12];
    float* out = (float*)d_out;

    bf16 *hb, *wq, *wk, *wv, *wo, *q, *k, *v, *attn;
    cudaGetSymbolAddress((void**)&hb,   g_hb);
    cudaGetSymbolAddress((void**)&wq,   g_wq);
    cudaGetSymbolAddress((void**)&wk,   g_wk);
    cudaGetSymbolAddress((void**)&wv,   g_wv);
    cudaGetSymbolAddress((void**)&wo,   g_wo);
    cudaGetSymbolAddress((void**)&q,    g_q);
    cudaGetSymbolAddress((void**)&k,    g_k);
    cudaGetSymbolAddress((void**)&v,    g_v);
    cudaGetSymbolAddress((void**)&attn, g_attn);

    // Unconditional (deterministic — no static guards allowed by harness rules)
    cudaFuncSetAttribute(gemm_bf16<0>, cudaFuncAttributeMaxDynamicSharedMemorySize, 65536);
    cudaFuncSetAttribute(gemm_bf16<1>, cudaFuncAttributeMaxDynamicSharedMemorySize, 65536);
    cudaFuncSetAttribute(flash_mma,    cudaFuncAttributeMaxDynamicSharedMemorySize, FLASH_SMEM);

    // convert fp32 -> bf16
    {
        int n4 = MTOT * DMODEL / 4;                       // hidden: 1,048,576 float4
        f2bf_kernel<<<(n4 + 255) / 256, 256>>>((const float4*)hidden, (bf162*)hb, n4);
        int w4 = DMODEL * DMODEL / 4;                     // 262,144 float4 each
        f2bf_kernel<<<(w4 + 255) / 256, 256>>>((const float4*)Wq, (bf162*)wq, w4);
        f2bf_kernel<<<(w4 + 255) / 256, 256>>>((const float4*)Wk, (bf162*)wk, w4);
        f2bf_kernel<<<(w4 + 255) / 256, 256>>>((const float4*)Wv, (bf162*)wv, w4);
        f2bf_kernel<<<(w4 + 255) / 256, 256>>>((const float4*)Wo, (bf162*)wo, w4);
    }

    dim3 pg(DMODEL / 128, MTOT / 128);   // (8, 32)
    gemm_bf16<0><<<pg, 256, 65536>>>(hb, wq, bq, nullptr, q, 0.125f);
    gemm_bf16<0><<<pg, 256, 65536>>>(hb, wk, bk, nullptr, k, 1.0f);
    gemm_bf16<0><<<pg, 256, 65536>>>(hb, wv, bv, nullptr, v, 1.0f);

    flash_mma<<<dim3(SEQ / 64, BATCH * NH), 128, FLASH_SMEM>>>(q, k, v, extra, mask, attn);

    gemm_bf16<1><<<pg, 256, 65536>>>(attn, wo, bo, hidden, out, 1.0f);
    ln_kernel<<<MTOT, 256>>>(out, gamma, beta);
}